// round 16
// baseline (speedup 1.0000x reference)
#include <cuda_runtime.h>
#include <cuda_fp16.h>
#include <cstdint>

#define N_EXP 16
#define MT_MAX 48
#define NTH 256
#define SA_ROWH 72                       // halves per A row (64 + 8 pad) = 144B
#define SA_BYTES (128 * SA_ROWH * 2)     // 18432
#define SB_ROWF 132                      // floats per B row (128 + 4 pad) = 528B
#define SB_BYTES (64 * SB_ROWF * 4)      // 33792
#define STG_BYTES (SA_BYTES + SB_BYTES)  // 52224
#define SMEM_BYTES (2 * STG_BYTES)       // 104448

// fp16 scratches (+128 pad rows so unmasked tail tiles stay in-bounds; pads are
// never written and __device__ globals are zero-initialized -> deterministic)
__device__ __half g_xh[(4096 + 128) * 1024];
__device__ __half g_acth[(4096 + 128) * 512];

__device__ __forceinline__ unsigned pkh2(float hi, float lo) {
    unsigned d;
    asm("cvt.rn.f16x2.f32 %0, %1, %2;" : "=r"(d) : "f"(hi), "f"(lo));
    return d;
}

__global__ void cvt_x_kernel(const float4* __restrict__ x) {
    unsigned id = blockIdx.x * blockDim.x + threadIdx.x;  // 1M float4 = full x
    float4 v = x[id];
    ((uint2*)g_xh)[id] = make_uint2(pkh2(v.y, v.x), pkh2(v.w, v.z));
}

__device__ __forceinline__ void mma_f16(float& d0, float& d1, float& d2, float& d3,
                                        unsigned a0, unsigned a1, unsigned a2, unsigned a3,
                                        unsigned b0, unsigned b1) {
    asm volatile(
        "mma.sync.aligned.m16n8k16.row.col.f32.f16.f16.f32 "
        "{%0,%1,%2,%3}, {%4,%5,%6,%7}, {%8,%9}, {%0,%1,%2,%3};\n"
        : "+f"(d0), "+f"(d1), "+f"(d2), "+f"(d3)
        : "r"(a0), "r"(a1), "r"(a2), "r"(a3), "r"(b0), "r"(b1));
}

__device__ __forceinline__ void ldm_x4(unsigned* r, unsigned addr) {
    asm volatile("ldmatrix.sync.aligned.m8n8.x4.shared.b16 {%0,%1,%2,%3}, [%4];"
                 : "=r"(r[0]), "=r"(r[1]), "=r"(r[2]), "=r"(r[3]) : "r"(addr));
}

// PASS2=0: gu GEMM. A=g_xh; B=gate_up[e] cols interleaved (g cols nf0..1, matching
//          u cols nf2..3); epilogue silu(g)*u -> g_acth (fp16).
// PASS2=1: down GEMM. A=g_acth; B=down[e]; epilogue fp32 -> C.
template <int KDIM, int PASS2>
__global__ __launch_bounds__(NTH, 2)
void moe_gemm(const float* __restrict__ Bw, const int* __restrict__ counts,
              float* __restrict__ C) {
    extern __shared__ char dsm[];
    const int tid = threadIdx.x;

    // ---- m-tile -> (expert, rows) ----
    int e = -1, m0 = 0, mEnd = 0;
    {
        int accT = 0, off = 0;
#pragma unroll
        for (int i = 0; i < N_EXP; i++) {
            int c = __ldg(counts + i);
            int nt = (c + 127) >> 7;
            if (e < 0 && (int)blockIdx.x < accT + nt) {
                e = i; m0 = off + (blockIdx.x - accT) * 128; mEnd = off + c;
            }
            accT += nt; off += c;
        }
    }
    if (e < 0) return;

    const int by = blockIdx.y;
    const int n0 = by * (PASS2 ? 128 : 64);
    const __half* Ah = PASS2 ? g_acth : g_xh;
    const int LDAh = PASS2 ? 512 : 1024;
    const float* Bp = Bw + (size_t)e * KDIM * 1024;

    const int lane = tid & 31, w = tid >> 5;
    const int wm = w & 1, wn = w >> 1;        // warp tile: 64m x 32n
    const int g = lane >> 2, tg = lane & 3;
    const int am = tid >> 1, ahc = tid & 1;   // A producer: row, half-of-row (32 halves)
    const int b_k = tid >> 2, b_c = tid & 3;  // B producer: k-row (64), chunk base

    // ldmatrix lane address pattern (reproduces scalar af layout)
    const int a_lrow = wm * 64 + (lane & 7) + 8 * ((lane >> 3) & 1);
    const int a_lcol = 8 * (lane >> 4);  // halves

    auto cpAB = [&](int t, int s) {
        // A: fp16, 64 halves/row staged as 4 x 16B per thread (2 threads/row)
        {
            const __half* src = Ah + (size_t)(m0 + am) * LDAh + t * 64 + ahc * 32;
            unsigned d0 = (unsigned)__cvta_generic_to_shared(
                dsm + s * STG_BYTES + am * (SA_ROWH * 2) + ahc * 64);
#pragma unroll
            for (int c = 0; c < 4; c++)
                asm volatile("cp.async.cg.shared.global [%0], [%1], 16;"
                             :: "r"(d0 + 16 * c), "l"(src + 8 * c));
        }
        // B: fp32, 64 k-rows; 8 x 16B per thread (4 threads/row)
        float* sB = (float*)(dsm + s * STG_BYTES + SA_BYTES);
#pragma unroll
        for (int p = 0; p < 8; p++) {
            int nl = b_c + 4 * p;  // 0..31
            int iext;
            if (PASS2) iext = n0 + 4 * nl;
            else       iext = n0 + ((nl >> 3) << 4) + ((nl & 3) << 2) + (((nl >> 2) & 1) << 9);
            const float* src = Bp + (size_t)(t * 64 + b_k) * 1024 + iext;
            unsigned dst = (unsigned)__cvta_generic_to_shared(sB + b_k * SB_ROWF + 4 * nl);
            asm volatile("cp.async.cg.shared.global [%0], [%1], 16;" :: "r"(dst), "l"(src));
        }
    };

    float acc4[4][4][4];
#pragma unroll
    for (int i = 0; i < 4; i++)
#pragma unroll
        for (int j = 0; j < 4; j++)
#pragma unroll
            for (int q = 0; q < 4; q++) acc4[i][j][q] = 0.f;

    auto compute = [&](int s) {
        const unsigned abase = (unsigned)__cvta_generic_to_shared(dsm + s * STG_BYTES) +
                               (a_lrow * SA_ROWH + a_lcol) * 2;
        const float* sB = (const float*)(dsm + s * STG_BYTES + SA_BYTES);
#pragma unroll
        for (int h = 0; h < 2; h++) {  // two 32-k half-windows
            // batched B: all fp32 loads + converts for this half hoisted off the MMA chain
            unsigned bf[2][4][2];
#pragma unroll
            for (int ks = 0; ks < 2; ks++)
#pragma unroll
                for (int nf = 0; nf < 4; nf++) {
                    int nb = wn * 32 + nf * 8 + g;
                    const float* c0 = sB + (h * 32 + ks * 16 + 2 * tg) * SB_ROWF + nb;
                    bf[ks][nf][0] = pkh2(c0[SB_ROWF], c0[0]);            // k+1 (hi), k (lo)
                    bf[ks][nf][1] = pkh2(c0[9 * SB_ROWF], c0[8 * SB_ROWF]);
                }
#pragma unroll
            for (int ks = 0; ks < 2; ks++) {
                unsigned af[4][4];
#pragma unroll
                for (int mf = 0; mf < 4; mf++)
                    ldm_x4(af[mf], abase + mf * (16 * SA_ROWH * 2) + h * 64 + ks * 32);
#pragma unroll
                for (int mf = 0; mf < 4; mf++)
#pragma unroll
                    for (int nf = 0; nf < 4; nf++)
                        mma_f16(acc4[mf][nf][0], acc4[mf][nf][1], acc4[mf][nf][2], acc4[mf][nf][3],
                                af[mf][0], af[mf][1], af[mf][2], af[mf][3],
                                bf[ks][nf][0], bf[ks][nf][1]);
            }
        }
    };

    // ---- 2-stage BK=64 mainloop, 1 sync per window, prefetch distance 1 ----
    const int KT = KDIM / 64;
    cpAB(0, 0);
    asm volatile("cp.async.commit_group;");
    for (int t = 0; t < KT; t++) {
        asm volatile("cp.async.wait_group 0;" ::: "memory");  // stage t landed
        __syncthreads();  // also: all warps done reading stage (t+1)&1 from iter t-1
        if (t + 1 < KT) {
            cpAB(t + 1, (t + 1) & 1);
            asm volatile("cp.async.commit_group;");
        }
        compute(t & 1);
    }

    // ---- epilogue ----
    if (!PASS2) {
        // nf 0..1 = g cols, nf 2..3 = matching u cols (same external col)
#pragma unroll
        for (int mf = 0; mf < 4; mf++) {
#pragma unroll
            for (int nf = 0; nf < 2; nf++) {
                int row = m0 + wm * 64 + mf * 16 + g;
                int col = by * 64 + wn * 16 + nf * 8 + 2 * tg;
                if (row < mEnd) {
                    float g0 = acc4[mf][nf][0], g1 = acc4[mf][nf][1];
                    float u0 = acc4[mf][nf + 2][0], u1 = acc4[mf][nf + 2][1];
                    float v0 = g0 / (1.f + __expf(-g0)) * u0;
                    float v1 = g1 / (1.f + __expf(-g1)) * u1;
                    *(unsigned*)(g_acth + (size_t)row * 512 + col) = pkh2(v1, v0);
                }
                if (row + 8 < mEnd) {
                    float g0 = acc4[mf][nf][2], g1 = acc4[mf][nf][3];
                    float u0 = acc4[mf][nf + 2][2], u1 = acc4[mf][nf + 2][3];
                    float v0 = g0 / (1.f + __expf(-g0)) * u0;
                    float v1 = g1 / (1.f + __expf(-g1)) * u1;
                    *(unsigned*)(g_acth + (size_t)(row + 8) * 512 + col) = pkh2(v1, v0);
                }
            }
        }
    } else {
#pragma unroll
        for (int mf = 0; mf < 4; mf++) {
#pragma unroll
            for (int nf = 0; nf < 4; nf++) {
                int row = m0 + wm * 64 + mf * 16 + g;
                int col = n0 + wn * 32 + nf * 8 + 2 * tg;
                if (row < mEnd) {
                    float2 v = make_float2(acc4[mf][nf][0], acc4[mf][nf][1]);
                    *(float2*)(C + (size_t)row * 1024 + col) = v;
                }
                if (row + 8 < mEnd) {
                    float2 v = make_float2(acc4[mf][nf][2], acc4[mf][nf][3]);
                    *(float2*)(C + (size_t)(row + 8) * 1024 + col) = v;
                }
            }
        }
    }
}

extern "C" void kernel_launch(void* const* d_in, const int* in_sizes, int n_in,
                              void* d_out, int out_size) {
    const float* x    = (const float*)d_in[0];  // [4096, 1024]
    const float* gup  = (const float*)d_in[1];  // [16, 1024, 1024]
    const float* down = (const float*)d_in[2];  // [16, 512, 1024]
    const int* counts = (const int*)d_in[3];    // [16]
    float* out = (float*)d_out;                 // [4096, 1024]

    cudaFuncSetAttribute(moe_gemm<1024, 0>, cudaFuncAttributeMaxDynamicSharedMemorySize, SMEM_BYTES);
    cudaFuncSetAttribute(moe_gemm<512, 1>, cudaFuncAttributeMaxDynamicSharedMemorySize, SMEM_BYTES);

    cvt_x_kernel<<<4096, 256>>>((const float4*)x);
    moe_gemm<1024, 0><<<dim3(MT_MAX, 8), NTH, SMEM_BYTES>>>(gup, counts, nullptr);
    moe_gemm<512, 1><<<dim3(MT_MAX, 8), NTH, SMEM_BYTES>>>(down, counts, out);
}

// round 17
// speedup vs baseline: 1.1119x; 1.1119x over previous
#include <cuda_runtime.h>
#include <cuda_fp16.h>
#include <cstdint>

#define N_EXP 16
#define MT_MAX 80                        // >= sum ceil(c_e/64) worst case (64+16)
#define NTH 256
#define SA_ROWH 40                       // halves per A row (32 + 8 pad) = 80B
#define SA_BYTES (64 * SA_ROWH * 2)      // 5120
#define SB_ROWF 132                      // floats per B row (128 + 4 pad) = 528B
#define SB_BYTES (32 * SB_ROWF * 4)      // 16896
#define STG_BYTES (SA_BYTES + SB_BYTES)  // 22016
#define SMEM_BYTES (2 * STG_BYTES)       // 44032

// fp16 scratches (+128 pad rows so unmasked tail tiles stay in-bounds; pads are
// never written and __device__ globals are zero-initialized -> deterministic)
__device__ __half g_xh[(4096 + 128) * 1024];
__device__ __half g_acth[(4096 + 128) * 512];

__device__ __forceinline__ unsigned pkh2(float hi, float lo) {
    unsigned d;
    asm("cvt.rn.f16x2.f32 %0, %1, %2;" : "=r"(d) : "f"(hi), "f"(lo));
    return d;
}

__global__ void cvt_x_kernel(const float4* __restrict__ x) {
    unsigned id = blockIdx.x * blockDim.x + threadIdx.x;  // 1M float4 = full x
    float4 v = x[id];
    ((uint2*)g_xh)[id] = make_uint2(pkh2(v.y, v.x), pkh2(v.w, v.z));
}

__device__ __forceinline__ void mma_f16(float& d0, float& d1, float& d2, float& d3,
                                        unsigned a0, unsigned a1, unsigned a2, unsigned a3,
                                        unsigned b0, unsigned b1) {
    asm volatile(
        "mma.sync.aligned.m16n8k16.row.col.f32.f16.f16.f32 "
        "{%0,%1,%2,%3}, {%4,%5,%6,%7}, {%8,%9}, {%0,%1,%2,%3};\n"
        : "+f"(d0), "+f"(d1), "+f"(d2), "+f"(d3)
        : "r"(a0), "r"(a1), "r"(a2), "r"(a3), "r"(b0), "r"(b1));
}

__device__ __forceinline__ void ldm_x4(unsigned* r, unsigned addr) {
    asm volatile("ldmatrix.sync.aligned.m8n8.x4.shared.b16 {%0,%1,%2,%3}, [%4];"
                 : "=r"(r[0]), "=r"(r[1]), "=r"(r[2]), "=r"(r[3]) : "r"(addr));
}

// 64-row m-tiles, 128 internal cols per CTA. Warp tile: 32m x 32n.
// PASS2=0: gu GEMM. A=g_xh; B=gate_up[e] cols interleaved (g cols nf0..1, matching
//          u cols nf2..3); epilogue silu(g)*u -> g_acth (fp16).
// PASS2=1: down GEMM. A=g_acth; B=down[e]; epilogue fp32 -> C.
template <int KDIM, int PASS2>
__global__ __launch_bounds__(NTH, 3)
void moe_gemm(const float* __restrict__ Bw, const int* __restrict__ counts,
              float* __restrict__ C) {
    extern __shared__ char dsm[];
    const int tid = threadIdx.x;

    // ---- m-tile (64 rows) -> (expert, rows) ----
    int e = -1, m0 = 0, mEnd = 0;
    {
        int accT = 0, off = 0;
#pragma unroll
        for (int i = 0; i < N_EXP; i++) {
            int c = __ldg(counts + i);
            int nt = (c + 63) >> 6;
            if (e < 0 && (int)blockIdx.x < accT + nt) {
                e = i; m0 = off + (blockIdx.x - accT) * 64; mEnd = off + c;
            }
            accT += nt; off += c;
        }
    }
    if (e < 0) return;

    const int by = blockIdx.y;
    const int n0 = by * (PASS2 ? 128 : 64);
    const __half* Ah = PASS2 ? g_acth : g_xh;
    const int LDAh = PASS2 ? 512 : 1024;
    const float* Bp = Bw + (size_t)e * KDIM * 1024;

    const int lane = tid & 31, w = tid >> 5;
    const int wm = w & 1, wn = w >> 1;        // warp tile: 32m x 32n
    const int g = lane >> 2, tg = lane & 3;
    const int am = tid >> 2, ahc = tid & 3;   // A producer: row (64), 16B chunk
    const int b_k = tid >> 3, b_c = tid & 7;  // B producer: k-row, chunk

    // ldmatrix lane address pattern (reproduces scalar af layout)
    const int a_lrow = wm * 32 + (lane & 7) + 8 * ((lane >> 3) & 1);
    const int a_lcol = 8 * (lane >> 4);  // halves

    auto cpAB = [&](int t, int s) {
        // A: fp16, 1 x 16B per thread (4 threads/row)
        {
            const __half* src = Ah + (size_t)(m0 + am) * LDAh + t * 32 + ahc * 8;
            unsigned d0 = (unsigned)__cvta_generic_to_shared(
                dsm + s * STG_BYTES + am * (SA_ROWH * 2) + ahc * 16);
            asm volatile("cp.async.cg.shared.global [%0], [%1], 16;" :: "r"(d0), "l"(src));
        }
        // B: fp32, 4 x 16B per thread
        float* sB = (float*)(dsm + s * STG_BYTES + SA_BYTES);
#pragma unroll
        for (int p = 0; p < 4; p++) {
            int nl = b_c + 8 * p;
            int iext;
            if (PASS2) iext = n0 + 4 * nl;
            else       iext = n0 + ((nl >> 3) << 4) + ((nl & 3) << 2) + (((nl >> 2) & 1) << 9);
            const float* src = Bp + (size_t)(t * 32 + b_k) * 1024 + iext;
            unsigned dst = (unsigned)__cvta_generic_to_shared(sB + b_k * SB_ROWF + 4 * nl);
            asm volatile("cp.async.cg.shared.global [%0], [%1], 16;" :: "r"(dst), "l"(src));
        }
    };

    float acc4[2][4][4];
#pragma unroll
    for (int i = 0; i < 2; i++)
#pragma unroll
        for (int j = 0; j < 4; j++)
#pragma unroll
            for (int q = 0; q < 4; q++) acc4[i][j][q] = 0.f;

    auto compute = [&](int s) {
        const unsigned abase = (unsigned)__cvta_generic_to_shared(dsm + s * STG_BYTES) +
                               (a_lrow * SA_ROWH + a_lcol) * 2;
        const float* sB = (const float*)(dsm + s * STG_BYTES + SA_BYTES);
        // batched B: all fp32 loads + converts hoisted, off the MMA chain
        unsigned bf[2][4][2];
#pragma unroll
        for (int ks = 0; ks < 2; ks++)
#pragma unroll
            for (int nf = 0; nf < 4; nf++) {
                int nb = wn * 32 + nf * 8 + g;
                const float* c0 = sB + (ks * 16 + 2 * tg) * SB_ROWF + nb;
                bf[ks][nf][0] = pkh2(c0[SB_ROWF], c0[0]);            // k+1 (hi), k (lo)
                bf[ks][nf][1] = pkh2(c0[9 * SB_ROWF], c0[8 * SB_ROWF]);
            }
#pragma unroll
        for (int ks = 0; ks < 2; ks++) {
            unsigned af[2][4];
#pragma unroll
            for (int mf = 0; mf < 2; mf++)
                ldm_x4(af[mf], abase + mf * (16 * SA_ROWH * 2) + ks * 32);
#pragma unroll
            for (int mf = 0; mf < 2; mf++)
#pragma unroll
                for (int nf = 0; nf < 4; nf++)
                    mma_f16(acc4[mf][nf][0], acc4[mf][nf][1], acc4[mf][nf][2], acc4[mf][nf][3],
                            af[mf][0], af[mf][1], af[mf][2], af[mf][3],
                            bf[ks][nf][0], bf[ks][nf][1]);
        }
    };

    // ---- 2-stage mainloop, 1 sync per ktile, prefetch distance 1 (R11 structure) ----
    const int KT = KDIM / 32;
    cpAB(0, 0);
    asm volatile("cp.async.commit_group;");
    for (int t = 0; t < KT; t++) {
        asm volatile("cp.async.wait_group 0;" ::: "memory");  // stage t landed
        __syncthreads();
        if (t + 1 < KT) {
            cpAB(t + 1, (t + 1) & 1);
            asm volatile("cp.async.commit_group;");
        }
        compute(t & 1);
    }

    // ---- epilogue ----
    if (!PASS2) {
        // nf 0..1 = g cols, nf 2..3 = matching u cols (same external col)
#pragma unroll
        for (int mf = 0; mf < 2; mf++) {
#pragma unroll
            for (int nf = 0; nf < 2; nf++) {
                int row = m0 + wm * 32 + mf * 16 + g;
                int col = by * 64 + wn * 16 + nf * 8 + 2 * tg;
                if (row < mEnd) {
                    float g0 = acc4[mf][nf][0], g1 = acc4[mf][nf][1];
                    float u0 = acc4[mf][nf + 2][0], u1 = acc4[mf][nf + 2][1];
                    float v0 = g0 / (1.f + __expf(-g0)) * u0;
                    float v1 = g1 / (1.f + __expf(-g1)) * u1;
                    *(unsigned*)(g_acth + (size_t)row * 512 + col) = pkh2(v1, v0);
                }
                if (row + 8 < mEnd) {
                    float g0 = acc4[mf][nf][2], g1 = acc4[mf][nf][3];
                    float u0 = acc4[mf][nf + 2][2], u1 = acc4[mf][nf + 2][3];
                    float v0 = g0 / (1.f + __expf(-g0)) * u0;
                    float v1 = g1 / (1.f + __expf(-g1)) * u1;
                    *(unsigned*)(g_acth + (size_t)(row + 8) * 512 + col) = pkh2(v1, v0);
                }
            }
        }
    } else {
#pragma unroll
        for (int mf = 0; mf < 2; mf++) {
#pragma unroll
            for (int nf = 0; nf < 4; nf++) {
                int row = m0 + wm * 32 + mf * 16 + g;
                int col = n0 + wn * 32 + nf * 8 + 2 * tg;
                if (row < mEnd) {
                    float2 v = make_float2(acc4[mf][nf][0], acc4[mf][nf][1]);
                    *(float2*)(C + (size_t)row * 1024 + col) = v;
                }
                if (row + 8 < mEnd) {
                    float2 v = make_float2(acc4[mf][nf][2], acc4[mf][nf][3]);
                    *(float2*)(C + (size_t)(row + 8) * 1024 + col) = v;
                }
            }
        }
    }
}

extern "C" void kernel_launch(void* const* d_in, const int* in_sizes, int n_in,
                              void* d_out, int out_size) {
    const float* x    = (const float*)d_in[0];  // [4096, 1024]
    const float* gup  = (const float*)d_in[1];  // [16, 1024, 1024]
    const float* down = (const float*)d_in[2];  // [16, 512, 1024]
    const int* counts = (const int*)d_in[3];    // [16]
    float* out = (float*)d_out;                 // [4096, 1024]

    cudaFuncSetAttribute(moe_gemm<1024, 0>, cudaFuncAttributeMaxDynamicSharedMemorySize, SMEM_BYTES);
    cudaFuncSetAttribute(moe_gemm<512, 1>, cudaFuncAttributeMaxDynamicSharedMemorySize, SMEM_BYTES);

    cvt_x_kernel<<<4096, 256>>>((const float4*)x);
    moe_gemm<1024, 0><<<dim3(MT_MAX, 8), NTH, SMEM_BYTES>>>(gup, counts, nullptr);
    moe_gemm<512, 1><<<dim3(MT_MAX, 8), NTH, SMEM_BYTES>>>(down, counts, out);
}